// round 1
// baseline (speedup 1.0000x reference)
#include <cuda_runtime.h>

// Problem: q,k,v: [2,12,2048,64] f32; mask: [2,1,1,2048] i32; bias: [1,12,2048,2048] f32
// Output: concat(out [2,12,2048,64], attn [2,12,2048,2048]) f32
//
// attn = softmax((q/8) @ k^T + bias, masked fill -10000 where mask==0)
// out  = attn @ v

#define TEMPERATURE 8.0f
#define NEG_FILL -10000.0f

constexpr int B = 2;
constexpr int H = 12;
constexpr int S = 2048;
constexpr int D = 64;
constexpr int TQ = 64;   // q rows per block
constexpr int TK = 64;   // k tile
constexpr int NKT = S / TK;  // 32

__global__ __launch_bounds__(256) void attn_fused_kernel(
    const float* __restrict__ q,
    const float* __restrict__ k,
    const float* __restrict__ v,
    const int*   __restrict__ mask,
    const float* __restrict__ bias,
    float* __restrict__ out,
    float* __restrict__ attn)
{
    // smA: pass1 = q tile [d][q], pass2 = e tile [k][q]
    // smB: pass1 = k tile [d][k], pass2 = v tile [k][d]
    __shared__ float smA[64][65];
    __shared__ float smB[64][65];
    __shared__ float red[TQ][16];
    __shared__ float row_m[TQ];
    __shared__ float row_s[TQ];
    __shared__ int   mask_s[S];

    const int t  = threadIdx.x;
    const int tx = t & 15;        // 0..15 -> k cols (pass1) / d cols (pass2)
    const int ty = t >> 4;        // 0..15 -> q rows
    const int bh = blockIdx.y;
    const int b  = bh / H;
    const int h  = bh % H;
    const int q0 = blockIdx.x * TQ;

    const float* qb    = q    + ((long)bh * S + q0) * D;
    const float* kb    = k    + (long)bh * S * D;
    const float* vb    = v    + (long)bh * S * D;
    float*       attb  = attn + ((long)bh * S + q0) * S;   // this block's 64 attn rows
    const float* biasb = bias + ((long)h  * S + q0) * S;

    // ---- load q tile (scaled by 1/T), layout [d][q] ----
    #pragma unroll
    for (int i = 0; i < 16; i++) {
        int idx = t + i * 256;
        int r = idx >> 6, d = idx & 63;
        smA[d][r] = qb[idx] * (1.0f / TEMPERATURE);
    }
    // ---- preload mask for this batch ----
    for (int i = t; i < S; i += 256) mask_s[i] = mask[b * S + i];

    float mloc[4];
    #pragma unroll
    for (int r = 0; r < 4; r++) mloc[r] = -3.0e38f;

    // ================= Pass 1: logits = qk^T + bias, masked; write raw logits; row max ==
    for (int kt = 0; kt < NKT; kt++) {
        __syncthreads();   // protect smB reuse (and first-iter smA/mask fill)
        const int k0 = kt * TK;
        #pragma unroll
        for (int i = 0; i < 16; i++) {
            int idx = t + i * 256;
            int r = idx >> 6, d = idx & 63;
            smB[d][r] = kb[(k0 + r) * D + d];   // [d][k]
        }
        __syncthreads();

        float acc[4][4];
        #pragma unroll
        for (int r = 0; r < 4; r++)
            #pragma unroll
            for (int c = 0; c < 4; c++) acc[r][c] = 0.0f;

        #pragma unroll 8
        for (int d = 0; d < 64; d++) {
            float a0 = smA[d][ty * 4 + 0];
            float a1 = smA[d][ty * 4 + 1];
            float a2 = smA[d][ty * 4 + 2];
            float a3 = smA[d][ty * 4 + 3];
            float b0 = smB[d][tx * 4 + 0];
            float b1 = smB[d][tx * 4 + 1];
            float b2 = smB[d][tx * 4 + 2];
            float b3 = smB[d][tx * 4 + 3];
            acc[0][0] += a0 * b0; acc[0][1] += a0 * b1; acc[0][2] += a0 * b2; acc[0][3] += a0 * b3;
            acc[1][0] += a1 * b0; acc[1][1] += a1 * b1; acc[1][2] += a1 * b2; acc[1][3] += a1 * b3;
            acc[2][0] += a2 * b0; acc[2][1] += a2 * b1; acc[2][2] += a2 * b2; acc[2][3] += a2 * b3;
            acc[3][0] += a3 * b0; acc[3][1] += a3 * b1; acc[3][2] += a3 * b2; acc[3][3] += a3 * b3;
        }

        // epilogue: bias, mask, write logits, running max
        const int kk = k0 + tx * 4;
        const int m0 = mask_s[kk + 0];
        const int m1 = mask_s[kk + 1];
        const int m2 = mask_s[kk + 2];
        const int m3 = mask_s[kk + 3];
        #pragma unroll
        for (int r = 0; r < 4; r++) {
            const int qq = ty * 4 + r;
            float4 bs = *(const float4*)(biasb + (long)qq * S + kk);
            float l0 = acc[r][0] + bs.x;
            float l1 = acc[r][1] + bs.y;
            float l2 = acc[r][2] + bs.z;
            float l3 = acc[r][3] + bs.w;
            if (m0 == 0) l0 = NEG_FILL;
            if (m1 == 0) l1 = NEG_FILL;
            if (m2 == 0) l2 = NEG_FILL;
            if (m3 == 0) l3 = NEG_FILL;
            float4 wr = make_float4(l0, l1, l2, l3);
            *(float4*)(attb + (long)qq * S + kk) = wr;
            mloc[r] = fmaxf(mloc[r], fmaxf(fmaxf(l0, l1), fmaxf(l2, l3)));
        }
    }

    // ---- row max reduce across the 16 tx threads per row ----
    #pragma unroll
    for (int r = 0; r < 4; r++) red[ty * 4 + r][tx] = mloc[r];
    __syncthreads();
    if (t < 64) {
        float m = red[t][0];
        #pragma unroll
        for (int j = 1; j < 16; j++) m = fmaxf(m, red[t][j]);
        row_m[t] = m;
        row_s[t] = 0.0f;
    }

    // ================= Pass 2: e = exp(l - m); row sums; out_acc = e @ v ===============
    float accO[4][4];
    #pragma unroll
    for (int r = 0; r < 4; r++)
        #pragma unroll
        for (int c = 0; c < 4; c++) accO[r][c] = 0.0f;

    for (int kt = 0; kt < NKT; kt++) {
        __syncthreads();   // protect smA/smB reuse from previous GEMM (and row_m init)
        const int k0 = kt * TK;
        // fill e tile, layout [k][q]
        #pragma unroll
        for (int i = 0; i < 4; i++) {
            int idx4 = t + i * 256;            // 1024 float4 = 4096 floats
            int r  = idx4 >> 4;                // q row 0..63
            int kk = (idx4 & 15) * 4;          // k col
            float4 l4 = *(const float4*)(attb + (long)r * S + k0 + kk);
            float m = row_m[r];
            smA[kk + 0][r] = __expf(l4.x - m);
            smA[kk + 1][r] = __expf(l4.y - m);
            smA[kk + 2][r] = __expf(l4.z - m);
            smA[kk + 3][r] = __expf(l4.w - m);
        }
        __syncthreads();
        // row sums (threads 0..63), then everyone fills v tile [k][d]
        if (t < 64) {
            float s0 = 0, s1 = 0, s2 = 0, s3 = 0;
            #pragma unroll 4
            for (int kk = 0; kk < 64; kk += 4) {
                s0 += smA[kk + 0][t];
                s1 += smA[kk + 1][t];
                s2 += smA[kk + 2][t];
                s3 += smA[kk + 3][t];
            }
            row_s[t] += (s0 + s1) + (s2 + s3);
        }
        #pragma unroll
        for (int i = 0; i < 16; i++) {
            int idx = t + i * 256;
            int r = idx >> 6, d = idx & 63;
            smB[r][d] = vb[(k0 + r) * D + d];   // [k][d]
        }
        __syncthreads();

        #pragma unroll 8
        for (int kk = 0; kk < 64; kk++) {
            float a0 = smA[kk][ty * 4 + 0];
            float a1 = smA[kk][ty * 4 + 1];
            float a2 = smA[kk][ty * 4 + 2];
            float a3 = smA[kk][ty * 4 + 3];
            float b0 = smB[kk][tx * 4 + 0];
            float b1 = smB[kk][tx * 4 + 1];
            float b2 = smB[kk][tx * 4 + 2];
            float b3 = smB[kk][tx * 4 + 3];
            accO[0][0] += a0 * b0; accO[0][1] += a0 * b1; accO[0][2] += a0 * b2; accO[0][3] += a0 * b3;
            accO[1][0] += a1 * b0; accO[1][1] += a1 * b1; accO[1][2] += a1 * b2; accO[1][3] += a1 * b3;
            accO[2][0] += a2 * b0; accO[2][1] += a2 * b1; accO[2][2] += a2 * b2; accO[2][3] += a2 * b3;
            accO[3][0] += a3 * b0; accO[3][1] += a3 * b1; accO[3][2] += a3 * b2; accO[3][3] += a3 * b3;
        }
    }

    __syncthreads();
    if (t < 64) row_s[t] = 1.0f / row_s[t];
    __syncthreads();

    // ================= Pass 3: write normalized attn and out ===========================
    for (int kt = 0; kt < NKT; kt++) {
        const int k0 = kt * TK;
        #pragma unroll
        for (int i = 0; i < 4; i++) {
            int idx4 = t + i * 256;
            int r  = idx4 >> 4;
            int kk = (idx4 & 15) * 4;
            float* p = attb + (long)r * S + k0 + kk;
            float4 l4 = *(const float4*)p;
            float m  = row_m[r];
            float rs = row_s[r];
            l4.x = __expf(l4.x - m) * rs;
            l4.y = __expf(l4.y - m) * rs;
            l4.z = __expf(l4.z - m) * rs;
            l4.w = __expf(l4.w - m) * rs;
            *(float4*)p = l4;
        }
    }

    #pragma unroll
    for (int r = 0; r < 4; r++) {
        const int qq = ty * 4 + r;
        const float rs = row_s[qq];
        float4 o = make_float4(accO[r][0] * rs, accO[r][1] * rs,
                               accO[r][2] * rs, accO[r][3] * rs);
        *(float4*)(out + ((long)bh * S + q0 + qq) * D + tx * 4) = o;
    }
}

extern "C" void kernel_launch(void* const* d_in, const int* in_sizes, int n_in,
                              void* d_out, int out_size) {
    const float* q    = (const float*)d_in[0];
    const float* k    = (const float*)d_in[1];
    const float* v    = (const float*)d_in[2];
    const int*   mask = (const int*)  d_in[3];
    const float* bias = (const float*)d_in[4];

    float* out  = (float*)d_out;                       // [B,H,S,D]
    float* attn = (float*)d_out + (long)B * H * S * D; // [B,H,S,S]

    dim3 grid(S / TQ, B * H);   // (32, 24)
    attn_fused_kernel<<<grid, 256>>>(q, k, v, mask, bias, out, attn);
}